// round 16
// baseline (speedup 1.0000x reference)
#include <cuda_runtime.h>
#include <cuda_bf16.h>
#include <cstdint>

// ---------------------------------------------------------------------------
// DeformableConv3D  (B=1, CIN=COUT=32, D=32, H=W=64, KS=3, stride=1, pad=1)
//
//  1. transpose x (C,D,H,W) -> xt (D,H,W,C)
//  2. reorg: conv weights -> split-bf16 B image; deform weights -> split-bf16
//     [27][64][40] image; bias
//  3. conv as HMMA bf16 split GEMM (R9 exact) -> offmask TRANSPOSED [108][NVOX]
//  4. deform12 = deform7 per-warp structure at 256 threads / 256 voxels per
//     block: 3 CTAs/SM x 8 warps = 24 resident warps (was 6x4 with more tail)
// ---------------------------------------------------------------------------

#define DD 32
#define HH 64
#define WW 64
#define NVOX (DD*HH*WW)
#define CIN 32
#define COUT 32
#define KK 27
#define OC108 108
#define OCP 128
#define AST 72          // A smem row stride (bf16)
#define BST 136         // conv B smem row stride (bf16)
#define WBS 40          // deform W image row stride (bf16)

typedef unsigned long long ull;

__device__ float g_xt[NVOX * CIN];                     // 16 MB channels-last x
__device__ __nv_bfloat16 g_wbf[KK * 64 * BST];         // conv B image per tap
__device__ __nv_bfloat16 g_wcb[KK * 64 * WBS];         // deform W image per tap
__device__ float g_bias128[OCP];
__device__ float g_offmask[(size_t)OC108 * NVOX];      // TRANSPOSED [comp][vox]

// ---------------- packed f32x2 helpers --------------------------------------
__device__ __forceinline__ ull pack2(float a, float b) {
    ull r;
    asm("mov.b64 %0, {%1, %2};"
        : "=l"(r) : "r"(__float_as_uint(a)), "r"(__float_as_uint(b)));
    return r;
}
__device__ __forceinline__ void unpack2(ull v, float& a, float& b) {
    unsigned int lo, hi;
    asm("mov.b64 {%0, %1}, %2;" : "=r"(lo), "=r"(hi) : "l"(v));
    a = __uint_as_float(lo); b = __uint_as_float(hi);
}
__device__ __forceinline__ void ffma2(ull& d, ull a, ull b) {
    asm("fma.rn.f32x2 %0, %1, %2, %0;" : "+l"(d) : "l"(a), "l"(b));
}

// ---------------- mma helpers -------------------------------------------------
__device__ __forceinline__ uint32_t smem_u32(const void* p) {
    uint32_t a;
    asm("{ .reg .u64 t; cvta.to.shared.u64 t, %1; cvt.u32.u64 %0, t; }"
        : "=r"(a) : "l"(p));
    return a;
}
__device__ __forceinline__ void ldmA(uint32_t a[4], uint32_t addr) {
    asm volatile("ldmatrix.sync.aligned.m8n8.x4.shared.b16 {%0,%1,%2,%3}, [%4];"
        : "=r"(a[0]), "=r"(a[1]), "=r"(a[2]), "=r"(a[3]) : "r"(addr));
}
__device__ __forceinline__ void ldmB(uint32_t b[2], uint32_t addr) {
    asm volatile("ldmatrix.sync.aligned.m8n8.x2.trans.shared.b16 {%0,%1}, [%2];"
        : "=r"(b[0]), "=r"(b[1]) : "r"(addr));
}
__device__ __forceinline__ void mma16816(float c[4], const uint32_t a[4],
                                         const uint32_t b[2]) {
    asm volatile(
        "mma.sync.aligned.m16n8k16.row.col.f32.bf16.bf16.f32 "
        "{%0,%1,%2,%3}, {%4,%5,%6,%7}, {%8,%9}, {%0,%1,%2,%3};"
        : "+f"(c[0]), "+f"(c[1]), "+f"(c[2]), "+f"(c[3])
        : "r"(a[0]), "r"(a[1]), "r"(a[2]), "r"(a[3]), "r"(b[0]), "r"(b[1]));
}
__device__ __forceinline__ uint32_t cvt_bf16x2(float h, float l) {
    uint32_t r;
    asm("cvt.rn.bf16x2.f32 %0, %1, %2;" : "=r"(r) : "f"(h), "f"(l));
    return r;
}
__device__ __forceinline__ void split_store(__nv_bfloat16* base, int row, int col,
                                            float4 xv) {
    uint32_t hp0 = cvt_bf16x2(xv.y, xv.x);
    uint32_t hp1 = cvt_bf16x2(xv.w, xv.z);
    float xh = __uint_as_float(hp0 << 16);
    float yh = __uint_as_float(hp0 & 0xFFFF0000u);
    float zh = __uint_as_float(hp1 << 16);
    float wh = __uint_as_float(hp1 & 0xFFFF0000u);
    uint32_t lp0 = cvt_bf16x2(xv.y - yh, xv.x - xh);
    uint32_t lp1 = cvt_bf16x2(xv.w - wh, xv.z - zh);
    *(uint2*)(base + row * AST + col)      = make_uint2(hp0, hp1);
    *(uint2*)(base + row * AST + 32 + col) = make_uint2(lp0, lp1);
}

// ---------------- 1. transpose ----------------------------------------------
__global__ void __launch_bounds__(256) transpose_kernel(const float* __restrict__ x) {
    __shared__ float s[32][33];
    int v0 = blockIdx.x * 32;
    int tx = threadIdx.x, ty = threadIdx.y;
#pragma unroll
    for (int i = 0; i < 4; i++) {
        int c = ty + 8 * i;
        s[c][tx] = x[c * NVOX + v0 + tx];
    }
    __syncthreads();
#pragma unroll
    for (int i = 0; i < 4; i++) {
        int vv = ty + 8 * i;
        g_xt[(size_t)(v0 + vv) * 32 + tx] = s[tx][vv];
    }
}

// ---------------- 2. weight / bias reorg -------------------------------------
__global__ void reorg_kernel(const float* __restrict__ w_off,
                             const float* __restrict__ b_off,
                             const float* __restrict__ w_mask,
                             const float* __restrict__ b_mask,
                             const float* __restrict__ w) {
    int idx = blockIdx.x * 256 + threadIdx.x;
    if (idx < KK * 64 * BST) {
        int tap = idx / (64 * BST);
        int rem = idx % (64 * BST);
        int r   = rem / BST;
        int n   = rem % BST;
        float out = 0.0f;
        if (n < OCP) {
            int cin = r & 31;
            float wv = 0.0f;
            if (n < 81)        wv = w_off [(n * CIN + cin) * KK + tap];
            else if (n < 108)  wv = w_mask[((n - 81) * CIN + cin) * KK + tap];
            __nv_bfloat16 hi = __float2bfloat16(wv);
            out = (r < 32) ? __bfloat162float(hi) : (wv - __bfloat162float(hi));
        }
        g_wbf[idx] = __float2bfloat16(out);
    }
    if (idx < KK * 64 * WBS) {
        int tap = idx / (64 * WBS);
        int rem = idx % (64 * WBS);
        int r   = rem / WBS;
        int n   = rem % WBS;
        float out = 0.0f;
        if (n < COUT) {
            int cin = r & 31;
            float wv = w[(n * CIN + cin) * KK + tap];
            __nv_bfloat16 hi = __float2bfloat16(wv);
            out = (r < 32) ? __bfloat162float(hi) : (wv - __bfloat162float(hi));
        }
        g_wcb[idx] = __float2bfloat16(out);
    }
    if (idx < OCP) {
        g_bias128[idx] = (idx < 81) ? b_off[idx]
                      : (idx < 108) ? b_mask[idx - 81] : 0.0f;
    }
}

// ---------------- 3. conv via HMMA bf16 split GEMM (R9 exact) ----------------
__global__ void __launch_bounds__(256) conv_hmma_kernel() {
    __shared__ __align__(16) __nv_bfloat16 As[128 * AST];
    __shared__ __align__(16) __nv_bfloat16 Bs[64 * BST];

    int t = threadIdx.x;
    int wid = t >> 5, lane = t & 31;
    int warp_m = wid >> 2;
    int warp_n = wid & 3;

    int v0 = blockIdx.x * 128;
    int z  = v0 >> 12;
    int y0 = (v0 >> 6) & 63;

    uint32_t as_b = smem_u32(As);
    uint32_t bs_b = smem_u32(Bs);

    int arow = lane & 15;
    int acol = (lane >> 4) << 3;
    uint32_t a_base = as_b + ((warp_m * 64 + arow) * AST + acol) * 2;
    uint32_t b_base = bs_b + (arow * BST + warp_n * 32) * 2;

    float c[4][4][4];
#pragma unroll
    for (int mt = 0; mt < 4; mt++)
#pragma unroll
        for (int nt = 0; nt < 4; nt++)
#pragma unroll
            for (int e = 0; e < 4; e++) c[mt][nt][e] = 0.0f;

#pragma unroll 1
    for (int tap = 0; tap < KK; tap++) {
        int kz = tap / 9, ky = (tap / 3) % 3, kx = tap % 3;
        {
            const float4* src = (const float4*)(g_wbf + (size_t)tap * 64 * BST);
            float4* dst = (float4*)Bs;
#pragma unroll
            for (int j = 0; j < 5; j++) {
                int idx = t + j * 256;
                if (idx < 64 * BST / 8) dst[idx] = __ldg(src + idx);
            }
        }
        {
            int zz = z + kz - 1;
            bool zok = (unsigned)zz < (unsigned)DD;
#pragma unroll
            for (int p = 0; p < 4; p++) {
                int slot = p * 256 + t;
                int vl = slot >> 3, c4 = slot & 7;
                int yy = y0 + (vl >> 6) + ky - 1;
                int xx = (vl & 63) + kx - 1;
                bool valid = zok && ((unsigned)yy < (unsigned)HH) &&
                             ((unsigned)xx < (unsigned)WW);
                float4 xv = valid
                    ? __ldg((const float4*)(g_xt +
                        (((size_t)(zz * HH + yy) * WW + xx) << 5)) + c4)
                    : make_float4(0.f, 0.f, 0.f, 0.f);
                split_store(As, vl, c4 * 4, xv);
            }
        }
        __syncthreads();

#pragma unroll
        for (int chunk = 0; chunk < 2; chunk++) {
            int kc = chunk * 16;
            uint32_t ah[4][4], al[4][4], bh[4][2], bl[4][2];
#pragma unroll
            for (int mt = 0; mt < 4; mt++)
                ldmA(ah[mt], a_base + (mt * 16 * AST + kc) * 2);
#pragma unroll
            for (int nt = 0; nt < 4; nt++)
                ldmB(bh[nt], b_base + (kc * BST + nt * 8) * 2);
#pragma unroll
            for (int mt = 0; mt < 4; mt++)
#pragma unroll
                for (int nt = 0; nt < 4; nt++)
                    mma16816(c[mt][nt], ah[mt], bh[nt]);
#pragma unroll
            for (int nt = 0; nt < 4; nt++)
                ldmB(bl[nt], b_base + ((32 + kc) * BST + nt * 8) * 2);
#pragma unroll
            for (int mt = 0; mt < 4; mt++)
#pragma unroll
                for (int nt = 0; nt < 4; nt++)
                    mma16816(c[mt][nt], ah[mt], bl[nt]);
#pragma unroll
            for (int mt = 0; mt < 4; mt++)
                ldmA(al[mt], a_base + (mt * 16 * AST + 32 + kc) * 2);
#pragma unroll
            for (int mt = 0; mt < 4; mt++)
#pragma unroll
                for (int nt = 0; nt < 4; nt++)
                    mma16816(c[mt][nt], al[mt], bh[nt]);
        }
        __syncthreads();
    }

    int gq = lane >> 2;
    int qq = lane & 3;
#pragma unroll
    for (int nt = 0; nt < 4; nt++) {
        int oc = warp_n * 32 + nt * 8 + qq * 2;
        if (oc >= OC108) continue;
        float b0 = g_bias128[oc], b1 = g_bias128[oc + 1];
        float* r0p = g_offmask + (size_t)oc * NVOX;
        float* r1p = g_offmask + (size_t)(oc + 1) * NVOX;
#pragma unroll
        for (int mt = 0; mt < 4; mt++) {
            int r0 = v0 + warp_m * 64 + mt * 16 + gq;
            float f0 = c[mt][nt][0] + b0;
            float f1 = c[mt][nt][1] + b1;
            float f2 = c[mt][nt][2] + b0;
            float f3 = c[mt][nt][3] + b1;
            if (oc     >= 81) { f0 = 1.f/(1.f+__expf(-f0)); f2 = 1.f/(1.f+__expf(-f2)); }
            if (oc + 1 >= 81) { f1 = 1.f/(1.f+__expf(-f1)); f3 = 1.f/(1.f+__expf(-f3)); }
            r0p[r0]     = f0;
            r1p[r0]     = f1;
            r0p[r0 + 8] = f2;
            r1p[r0 + 8] = f3;
        }
    }
}

// ---------------- 4. deform12: deform7 structure at 256 thr / 256 vox --------
__global__ void __launch_bounds__(256) deform12_kernel(const float* __restrict__ bfin,
                                                       float* __restrict__ out) {
    __shared__ __align__(16) __nv_bfloat16 As[256 * AST];     // 36864 B
    __shared__ __align__(16) __nv_bfloat16 Wb[2][64 * WBS];   // 2 x 5120 B
    __shared__ ull WA[8][256];                                // 16384 B

    int t  = threadIdx.x;
    int wid = t >> 5, lane = t & 31;
    int v0 = blockIdx.x * 256;
    int v  = v0 + t;                       // lane-owned voxel
    int xw = v & 63, y = (v >> 6) & 63, z = v >> 12;

    uint32_t as_b = smem_u32(As);
    int arow = lane & 15;
    int acol = (lane >> 4) << 3;
    uint32_t a_base = as_b + ((wid * 32 + arow) * AST + acol) * 2;

    float c2[2][4][4];
#pragma unroll
    for (int mt = 0; mt < 2; mt++)
#pragma unroll
        for (int nt = 0; nt < 4; nt++)
#pragma unroll
            for (int e = 0; e < 4; e++) c2[mt][nt][e] = 0.0f;

#pragma unroll 1
    for (int kt = 0; kt < KK; kt++) {
        int kz = kt / 9, ky = (kt / 3) % 3, kx = kt % 3;
        int buf = kt & 1;

        // stage this tap's split-bf16 weights (double-buffered)
        {
            const float4* src = (const float4*)(g_wcb + (size_t)kt * 64 * WBS);
            float4* dst = (float4*)Wb[buf];
#pragma unroll
            for (int j = 0; j < 2; j++) {
                int idx = t + j * 256;
                if (idx < 64 * WBS / 8) dst[idx] = __ldg(src + idx);
            }
        }
        __syncthreads();

        // --- phase A: per-lane corner precompute -> packed smem table
        {
            float oz = __ldg(g_offmask + (size_t)kt        * NVOX + v);
            float oy = __ldg(g_offmask + (size_t)(27 + kt) * NVOX + v);
            float ox = __ldg(g_offmask + (size_t)(54 + kt) * NVOX + v);
            float m  = __ldg(g_offmask + (size_t)(81 + kt) * NVOX + v);

            float zc = (float)(z - 1 + kz) + oz;
            float yc = (float)(y - 1 + ky) + oy;
            float xc = (float)(xw - 1 + kx) + ox;

            float zf0 = floorf(zc), yf0 = floorf(yc), xf0 = floorf(xc);
            float fz = zc - zf0, fy = yc - yf0, fx = xc - xf0;
            int z0 = (int)zf0, y0i = (int)yf0, x0 = (int)xf0;

            float wz[2], wy[2], wx[2];
            int zi[2], yi[2], xi[2];
            wz[0] = (1.f - fz) * m; wz[1] = fz * m;
            wy[0] = 1.f - fy;       wy[1] = fy;
            wx[0] = 1.f - fx;       wx[1] = fx;
#pragma unroll
            for (int d = 0; d < 2; d++) {
                int zz = z0 + d, yyi = y0i + d, xxi = x0 + d;
                if ((unsigned)zz  >= (unsigned)DD) wz[d] = 0.f;
                if ((unsigned)yyi >= (unsigned)HH) wy[d] = 0.f;
                if ((unsigned)xxi >= (unsigned)WW) wx[d] = 0.f;
                zi[d] = min(max(zz, 0), DD - 1);
                yi[d] = min(max(yyi, 0), HH - 1);
                xi[d] = min(max(xxi, 0), WW - 1);
            }
#pragma unroll
            for (int cc = 0; cc < 8; cc++) {
                int dz = cc >> 2, dy = (cc >> 1) & 1, dx = cc & 1;
                float wgt = wz[dz] * wy[dy] * wx[dx];
                uint32_t a = (uint32_t)((zi[dz] * HH + yi[dy]) * WW + xi[dx]);
                WA[cc][t] = pack2(wgt, __uint_as_float(a));
            }
        }
        __syncwarp();

        // --- phase B: warp-local sampling (LDS.64 broadcast, full gather MLP)
#pragma unroll 2
        for (int p = 0; p < 8; p++) {
            int vl = p * 4 + (lane >> 3);      // voxel row within warp
            int row = wid * 32 + vl;
            int c4 = lane & 7;

            ull s0 = 0ull, s1 = 0ull;
#pragma unroll
            for (int cc = 0; cc < 8; cc++) {
                float wgt, af;
                unpack2(WA[cc][row], wgt, af);
                uint32_t a = __float_as_uint(af);
                ulonglong2 g = __ldg((const ulonglong2*)
                    (g_xt + ((size_t)a << 5) + c4 * 4));
                ull w2 = pack2(wgt, wgt);
                ffma2(s0, w2, g.x);
                ffma2(s1, w2, g.y);
            }
            float f0, f1, f2, f3;
            unpack2(s0, f0, f1);
            unpack2(s1, f2, f3);
            split_store(As, row, c4 * 4, make_float4(f0, f1, f2, f3));
        }
        __syncwarp();

        // --- phase C: HMMA contraction (3 split products x 2 k-chunks)
        uint32_t wb_b = smem_u32(Wb[buf]);
        uint32_t b_base = wb_b + (arow * WBS) * 2;
#pragma unroll
        for (int pr = 0; pr < 3; pr++) {
            int aoff = (pr == 2) ? 32 : 0;
            int boff = (pr == 1) ? 32 : 0;
#pragma unroll
            for (int chunk = 0; chunk < 2; chunk++) {
                int kc = chunk * 16;
                uint32_t a[2][4], bb[4][2];
#pragma unroll
                for (int mt = 0; mt < 2; mt++)
                    ldmA(a[mt], a_base + (mt * 16 * AST + aoff + kc) * 2);
#pragma unroll
                for (int nt = 0; nt < 4; nt++)
                    ldmB(bb[nt], b_base + ((boff + kc) * WBS + nt * 8) * 2);
#pragma unroll
                for (int mt = 0; mt < 2; mt++)
#pragma unroll
                    for (int nt = 0; nt < 4; nt++)
                        mma16816(c2[mt][nt], a[mt], bb[nt]);
            }
        }
        __syncwarp();
    }

    // --- epilogue: + bias, store out[oc][v]
    int gq = lane >> 2;
    int qq = lane & 3;
#pragma unroll
    for (int nt = 0; nt < 4; nt++) {
        int oc = nt * 8 + qq * 2;
        float b0 = __ldg(bfin + oc), b1 = __ldg(bfin + oc + 1);
        float* r0p = out + (size_t)oc * NVOX;
        float* r1p = out + (size_t)(oc + 1) * NVOX;
#pragma unroll
        for (int mt = 0; mt < 2; mt++) {
            int vv = v0 + wid * 32 + mt * 16 + gq;
            r0p[vv]     = c2[mt][nt][0] + b0;
            r1p[vv]     = c2[mt][nt][1] + b1;
            r0p[vv + 8] = c2[mt][nt][2] + b0;
            r1p[vv + 8] = c2[mt][nt][3] + b1;
        }
    }
}

// ---------------------------------------------------------------------------
static const float* pick(void* const* d_in, const int* in_sizes, int n_in, int want) {
    for (int i = 0; i < n_in; i++)
        if (in_sizes[i] == want) return (const float*)d_in[i];
    return nullptr;
}

extern "C" void kernel_launch(void* const* d_in, const int* in_sizes, int n_in,
                              void* d_out, int out_size) {
    const float* x      = pick(d_in, in_sizes, n_in, NVOX * CIN);
    const float* w_off  = pick(d_in, in_sizes, n_in, 81 * CIN * KK);
    const float* b_off  = pick(d_in, in_sizes, n_in, 81);
    const float* w_mask = pick(d_in, in_sizes, n_in, 27 * CIN * KK);
    const float* b_mask = pick(d_in, in_sizes, n_in, 27);
    const float* w      = pick(d_in, in_sizes, n_in, COUT * CIN * KK);
    const float* b      = pick(d_in, in_sizes, n_in, COUT);
    float* out = (float*)d_out;

    transpose_kernel<<<NVOX / 32, dim3(32, 8)>>>(x);
    reorg_kernel<<<(KK * 64 * BST + 255) / 256, 256>>>(w_off, b_off, w_mask, b_mask, w);
    conv_hmma_kernel<<<NVOX / 128, 256>>>();
    deform12_kernel<<<NVOX / 256, 256>>>(b, out);
}

// round 17
// speedup vs baseline: 1.1938x; 1.1938x over previous
#include <cuda_runtime.h>
#include <cuda_bf16.h>
#include <cstdint>

// ---------------------------------------------------------------------------
// DeformableConv3D  (B=1, CIN=COUT=32, D=32, H=W=64, KS=3, stride=1, pad=1)
//
//  1. transpose x (C,D,H,W) -> xt (D,H,W,C)
//  2. reorg: conv weights -> split-bf16 B image; deform weights -> split-bf16
//     [27][64][40] image; bias
//  3. conv as HMMA bf16 split GEMM (R9 exact) -> offmask TRANSPOSED [108][NVOX]
//  4. deform13 = deform7 with single-buffer Wb (31KB smem) + launch_bounds
//     (128,7): 7 CTAs/SM -> 1036 concurrent blocks >= 1024 grid = ONE wave
// ---------------------------------------------------------------------------

#define DD 32
#define HH 64
#define WW 64
#define NVOX (DD*HH*WW)
#define CIN 32
#define COUT 32
#define KK 27
#define OC108 108
#define OCP 128
#define AST 72          // A smem row stride (bf16)
#define BST 136         // conv B smem row stride (bf16)
#define WBS 40          // deform W image row stride (bf16)

typedef unsigned long long ull;

__device__ float g_xt[NVOX * CIN];                     // 16 MB channels-last x
__device__ __nv_bfloat16 g_wbf[KK * 64 * BST];         // conv B image per tap
__device__ __nv_bfloat16 g_wcb[KK * 64 * WBS];         // deform W image per tap
__device__ float g_bias128[OCP];
__device__ float g_offmask[(size_t)OC108 * NVOX];      // TRANSPOSED [comp][vox]

// ---------------- packed f32x2 helpers --------------------------------------
__device__ __forceinline__ ull pack2(float a, float b) {
    ull r;
    asm("mov.b64 %0, {%1, %2};"
        : "=l"(r) : "r"(__float_as_uint(a)), "r"(__float_as_uint(b)));
    return r;
}
__device__ __forceinline__ void unpack2(ull v, float& a, float& b) {
    unsigned int lo, hi;
    asm("mov.b64 {%0, %1}, %2;" : "=r"(lo), "=r"(hi) : "l"(v));
    a = __uint_as_float(lo); b = __uint_as_float(hi);
}
__device__ __forceinline__ void ffma2(ull& d, ull a, ull b) {
    asm("fma.rn.f32x2 %0, %1, %2, %0;" : "+l"(d) : "l"(a), "l"(b));
}

// ---------------- mma helpers -------------------------------------------------
__device__ __forceinline__ uint32_t smem_u32(const void* p) {
    uint32_t a;
    asm("{ .reg .u64 t; cvta.to.shared.u64 t, %1; cvt.u32.u64 %0, t; }"
        : "=r"(a) : "l"(p));
    return a;
}
__device__ __forceinline__ void ldmA(uint32_t a[4], uint32_t addr) {
    asm volatile("ldmatrix.sync.aligned.m8n8.x4.shared.b16 {%0,%1,%2,%3}, [%4];"
        : "=r"(a[0]), "=r"(a[1]), "=r"(a[2]), "=r"(a[3]) : "r"(addr));
}
__device__ __forceinline__ void ldmB(uint32_t b[2], uint32_t addr) {
    asm volatile("ldmatrix.sync.aligned.m8n8.x2.trans.shared.b16 {%0,%1}, [%2];"
        : "=r"(b[0]), "=r"(b[1]) : "r"(addr));
}
__device__ __forceinline__ void mma16816(float c[4], const uint32_t a[4],
                                         const uint32_t b[2]) {
    asm volatile(
        "mma.sync.aligned.m16n8k16.row.col.f32.bf16.bf16.f32 "
        "{%0,%1,%2,%3}, {%4,%5,%6,%7}, {%8,%9}, {%0,%1,%2,%3};"
        : "+f"(c[0]), "+f"(c[1]), "+f"(c[2]), "+f"(c[3])
        : "r"(a[0]), "r"(a[1]), "r"(a[2]), "r"(a[3]), "r"(b[0]), "r"(b[1]));
}
__device__ __forceinline__ uint32_t cvt_bf16x2(float h, float l) {
    uint32_t r;
    asm("cvt.rn.bf16x2.f32 %0, %1, %2;" : "=r"(r) : "f"(h), "f"(l));
    return r;
}
__device__ __forceinline__ void split_store(__nv_bfloat16* base, int row, int col,
                                            float4 xv) {
    uint32_t hp0 = cvt_bf16x2(xv.y, xv.x);
    uint32_t hp1 = cvt_bf16x2(xv.w, xv.z);
    float xh = __uint_as_float(hp0 << 16);
    float yh = __uint_as_float(hp0 & 0xFFFF0000u);
    float zh = __uint_as_float(hp1 << 16);
    float wh = __uint_as_float(hp1 & 0xFFFF0000u);
    uint32_t lp0 = cvt_bf16x2(xv.y - yh, xv.x - xh);
    uint32_t lp1 = cvt_bf16x2(xv.w - wh, xv.z - zh);
    *(uint2*)(base + row * AST + col)      = make_uint2(hp0, hp1);
    *(uint2*)(base + row * AST + 32 + col) = make_uint2(lp0, lp1);
}

// ---------------- 1. transpose ----------------------------------------------
__global__ void __launch_bounds__(256) transpose_kernel(const float* __restrict__ x) {
    __shared__ float s[32][33];
    int v0 = blockIdx.x * 32;
    int tx = threadIdx.x, ty = threadIdx.y;
#pragma unroll
    for (int i = 0; i < 4; i++) {
        int c = ty + 8 * i;
        s[c][tx] = x[c * NVOX + v0 + tx];
    }
    __syncthreads();
#pragma unroll
    for (int i = 0; i < 4; i++) {
        int vv = ty + 8 * i;
        g_xt[(size_t)(v0 + vv) * 32 + tx] = s[tx][vv];
    }
}

// ---------------- 2. weight / bias reorg -------------------------------------
__global__ void reorg_kernel(const float* __restrict__ w_off,
                             const float* __restrict__ b_off,
                             const float* __restrict__ w_mask,
                             const float* __restrict__ b_mask,
                             const float* __restrict__ w) {
    int idx = blockIdx.x * 256 + threadIdx.x;
    if (idx < KK * 64 * BST) {
        int tap = idx / (64 * BST);
        int rem = idx % (64 * BST);
        int r   = rem / BST;
        int n   = rem % BST;
        float out = 0.0f;
        if (n < OCP) {
            int cin = r & 31;
            float wv = 0.0f;
            if (n < 81)        wv = w_off [(n * CIN + cin) * KK + tap];
            else if (n < 108)  wv = w_mask[((n - 81) * CIN + cin) * KK + tap];
            __nv_bfloat16 hi = __float2bfloat16(wv);
            out = (r < 32) ? __bfloat162float(hi) : (wv - __bfloat162float(hi));
        }
        g_wbf[idx] = __float2bfloat16(out);
    }
    if (idx < KK * 64 * WBS) {
        int tap = idx / (64 * WBS);
        int rem = idx % (64 * WBS);
        int r   = rem / WBS;
        int n   = rem % WBS;
        float out = 0.0f;
        if (n < COUT) {
            int cin = r & 31;
            float wv = w[(n * CIN + cin) * KK + tap];
            __nv_bfloat16 hi = __float2bfloat16(wv);
            out = (r < 32) ? __bfloat162float(hi) : (wv - __bfloat162float(hi));
        }
        g_wcb[idx] = __float2bfloat16(out);
    }
    if (idx < OCP) {
        g_bias128[idx] = (idx < 81) ? b_off[idx]
                      : (idx < 108) ? b_mask[idx - 81] : 0.0f;
    }
}

// ---------------- 3. conv via HMMA bf16 split GEMM (R9 exact) ----------------
__global__ void __launch_bounds__(256) conv_hmma_kernel() {
    __shared__ __align__(16) __nv_bfloat16 As[128 * AST];
    __shared__ __align__(16) __nv_bfloat16 Bs[64 * BST];

    int t = threadIdx.x;
    int wid = t >> 5, lane = t & 31;
    int warp_m = wid >> 2;
    int warp_n = wid & 3;

    int v0 = blockIdx.x * 128;
    int z  = v0 >> 12;
    int y0 = (v0 >> 6) & 63;

    uint32_t as_b = smem_u32(As);
    uint32_t bs_b = smem_u32(Bs);

    int arow = lane & 15;
    int acol = (lane >> 4) << 3;
    uint32_t a_base = as_b + ((warp_m * 64 + arow) * AST + acol) * 2;
    uint32_t b_base = bs_b + (arow * BST + warp_n * 32) * 2;

    float c[4][4][4];
#pragma unroll
    for (int mt = 0; mt < 4; mt++)
#pragma unroll
        for (int nt = 0; nt < 4; nt++)
#pragma unroll
            for (int e = 0; e < 4; e++) c[mt][nt][e] = 0.0f;

#pragma unroll 1
    for (int tap = 0; tap < KK; tap++) {
        int kz = tap / 9, ky = (tap / 3) % 3, kx = tap % 3;
        {
            const float4* src = (const float4*)(g_wbf + (size_t)tap * 64 * BST);
            float4* dst = (float4*)Bs;
#pragma unroll
            for (int j = 0; j < 5; j++) {
                int idx = t + j * 256;
                if (idx < 64 * BST / 8) dst[idx] = __ldg(src + idx);
            }
        }
        {
            int zz = z + kz - 1;
            bool zok = (unsigned)zz < (unsigned)DD;
#pragma unroll
            for (int p = 0; p < 4; p++) {
                int slot = p * 256 + t;
                int vl = slot >> 3, c4 = slot & 7;
                int yy = y0 + (vl >> 6) + ky - 1;
                int xx = (vl & 63) + kx - 1;
                bool valid = zok && ((unsigned)yy < (unsigned)HH) &&
                             ((unsigned)xx < (unsigned)WW);
                float4 xv = valid
                    ? __ldg((const float4*)(g_xt +
                        (((size_t)(zz * HH + yy) * WW + xx) << 5)) + c4)
                    : make_float4(0.f, 0.f, 0.f, 0.f);
                split_store(As, vl, c4 * 4, xv);
            }
        }
        __syncthreads();

#pragma unroll
        for (int chunk = 0; chunk < 2; chunk++) {
            int kc = chunk * 16;
            uint32_t ah[4][4], al[4][4], bh[4][2], bl[4][2];
#pragma unroll
            for (int mt = 0; mt < 4; mt++)
                ldmA(ah[mt], a_base + (mt * 16 * AST + kc) * 2);
#pragma unroll
            for (int nt = 0; nt < 4; nt++)
                ldmB(bh[nt], b_base + (kc * BST + nt * 8) * 2);
#pragma unroll
            for (int mt = 0; mt < 4; mt++)
#pragma unroll
                for (int nt = 0; nt < 4; nt++)
                    mma16816(c[mt][nt], ah[mt], bh[nt]);
#pragma unroll
            for (int nt = 0; nt < 4; nt++)
                ldmB(bl[nt], b_base + ((32 + kc) * BST + nt * 8) * 2);
#pragma unroll
            for (int mt = 0; mt < 4; mt++)
#pragma unroll
                for (int nt = 0; nt < 4; nt++)
                    mma16816(c[mt][nt], ah[mt], bl[nt]);
#pragma unroll
            for (int mt = 0; mt < 4; mt++)
                ldmA(al[mt], a_base + (mt * 16 * AST + 32 + kc) * 2);
#pragma unroll
            for (int mt = 0; mt < 4; mt++)
#pragma unroll
                for (int nt = 0; nt < 4; nt++)
                    mma16816(c[mt][nt], al[mt], bh[nt]);
        }
        __syncthreads();
    }

    int gq = lane >> 2;
    int qq = lane & 3;
#pragma unroll
    for (int nt = 0; nt < 4; nt++) {
        int oc = warp_n * 32 + nt * 8 + qq * 2;
        if (oc >= OC108) continue;
        float b0 = g_bias128[oc], b1 = g_bias128[oc + 1];
        float* r0p = g_offmask + (size_t)oc * NVOX;
        float* r1p = g_offmask + (size_t)(oc + 1) * NVOX;
#pragma unroll
        for (int mt = 0; mt < 4; mt++) {
            int r0 = v0 + warp_m * 64 + mt * 16 + gq;
            float f0 = c[mt][nt][0] + b0;
            float f1 = c[mt][nt][1] + b1;
            float f2 = c[mt][nt][2] + b0;
            float f3 = c[mt][nt][3] + b1;
            if (oc     >= 81) { f0 = 1.f/(1.f+__expf(-f0)); f2 = 1.f/(1.f+__expf(-f2)); }
            if (oc + 1 >= 81) { f1 = 1.f/(1.f+__expf(-f1)); f3 = 1.f/(1.f+__expf(-f3)); }
            r0p[r0]     = f0;
            r1p[r0]     = f1;
            r0p[r0 + 8] = f2;
            r1p[r0 + 8] = f3;
        }
    }
}

// ---------------- 4. deform13: deform7 + single Wb buffer, 7 CTAs/SM ---------
__global__ void __launch_bounds__(128, 7) deform13_kernel(
        const float* __restrict__ bfin, float* __restrict__ out) {
    __shared__ __align__(16) __nv_bfloat16 As[128 * AST];     // 18432 B
    __shared__ __align__(16) __nv_bfloat16 Wb[64 * WBS];      // 5120 B
    __shared__ ull WA[8][128];                                // 8192 B  (31.7KB)

    int t  = threadIdx.x;
    int wid = t >> 5, lane = t & 31;
    int v0 = blockIdx.x * 128;
    int v  = v0 + t;                       // lane-owned voxel
    int xw = v & 63, y = (v >> 6) & 63, z = v >> 12;

    uint32_t as_b = smem_u32(As);
    int arow = lane & 15;
    int acol = (lane >> 4) << 3;
    uint32_t a_base = as_b + ((wid * 32 + arow) * AST + acol) * 2;
    uint32_t wb_b = smem_u32(Wb);
    uint32_t b_base0 = wb_b + (arow * WBS) * 2;

    float c2[2][4][4];
#pragma unroll
    for (int mt = 0; mt < 2; mt++)
#pragma unroll
        for (int nt = 0; nt < 4; nt++)
#pragma unroll
            for (int e = 0; e < 4; e++) c2[mt][nt][e] = 0.0f;

#pragma unroll 1
    for (int kt = 0; kt < KK; kt++) {
        int kz = kt / 9, ky = (kt / 3) % 3, kx = kt % 3;

        // all prior-tap Wb readers must be done before overwrite
        __syncthreads();

        // stage this tap's split-bf16 weights (single buffer)
        {
            const float4* src = (const float4*)(g_wcb + (size_t)kt * 64 * WBS);
            float4* dst = (float4*)Wb;
#pragma unroll
            for (int j = 0; j < 3; j++) {
                int idx = t + j * 128;
                if (idx < 64 * WBS / 8) dst[idx] = __ldg(src + idx);
            }
        }

        // --- phase A: per-lane corner precompute -> packed smem table
        // (runs between the two block syncs; does not touch Wb)
        {
            float oz = __ldg(g_offmask + (size_t)kt        * NVOX + v);
            float oy = __ldg(g_offmask + (size_t)(27 + kt) * NVOX + v);
            float ox = __ldg(g_offmask + (size_t)(54 + kt) * NVOX + v);
            float m  = __ldg(g_offmask + (size_t)(81 + kt) * NVOX + v);

            float zc = (float)(z - 1 + kz) + oz;
            float yc = (float)(y - 1 + ky) + oy;
            float xc = (float)(xw - 1 + kx) + ox;

            float zf0 = floorf(zc), yf0 = floorf(yc), xf0 = floorf(xc);
            float fz = zc - zf0, fy = yc - yf0, fx = xc - xf0;
            int z0 = (int)zf0, y0i = (int)yf0, x0 = (int)xf0;

            float wz[2], wy[2], wx[2];
            int zi[2], yi[2], xi[2];
            wz[0] = (1.f - fz) * m; wz[1] = fz * m;
            wy[0] = 1.f - fy;       wy[1] = fy;
            wx[0] = 1.f - fx;       wx[1] = fx;
#pragma unroll
            for (int d = 0; d < 2; d++) {
                int zz = z0 + d, yyi = y0i + d, xxi = x0 + d;
                if ((unsigned)zz  >= (unsigned)DD) wz[d] = 0.f;
                if ((unsigned)yyi >= (unsigned)HH) wy[d] = 0.f;
                if ((unsigned)xxi >= (unsigned)WW) wx[d] = 0.f;
                zi[d] = min(max(zz, 0), DD - 1);
                yi[d] = min(max(yyi, 0), HH - 1);
                xi[d] = min(max(xxi, 0), WW - 1);
            }
#pragma unroll
            for (int cc = 0; cc < 8; cc++) {
                int dz = cc >> 2, dy = (cc >> 1) & 1, dx = cc & 1;
                float wgt = wz[dz] * wy[dy] * wx[dx];
                uint32_t a = (uint32_t)((zi[dz] * HH + yi[dy]) * WW + xi[dx]);
                WA[cc][t] = pack2(wgt, __uint_as_float(a));
            }
        }
        __syncthreads();   // Wb staged + WA visible (block-wide, conservative)

        // --- phase B: warp-local sampling (LDS.64 broadcast, full gather MLP)
#pragma unroll 2
        for (int p = 0; p < 8; p++) {
            int vl = p * 4 + (lane >> 3);      // voxel row within warp
            int row = wid * 32 + vl;
            int c4 = lane & 7;

            ull s0 = 0ull, s1 = 0ull;
#pragma unroll
            for (int cc = 0; cc < 8; cc++) {
                float wgt, af;
                unpack2(WA[cc][row], wgt, af);
                uint32_t a = __float_as_uint(af);
                ulonglong2 g = __ldg((const ulonglong2*)
                    (g_xt + ((size_t)a << 5) + c4 * 4));
                ull w2 = pack2(wgt, wgt);
                ffma2(s0, w2, g.x);
                ffma2(s1, w2, g.y);
            }
            float f0, f1, f2, f3;
            unpack2(s0, f0, f1);
            unpack2(s1, f2, f3);
            split_store(As, row, c4 * 4, make_float4(f0, f1, f2, f3));
        }
        __syncwarp();

        // --- phase C: HMMA contraction (3 split products x 2 k-chunks)
#pragma unroll
        for (int pr = 0; pr < 3; pr++) {
            int aoff = (pr == 2) ? 32 : 0;
            int boff = (pr == 1) ? 32 : 0;
#pragma unroll
            for (int chunk = 0; chunk < 2; chunk++) {
                int kc = chunk * 16;
                uint32_t a[2][4], bb[4][2];
#pragma unroll
                for (int mt = 0; mt < 2; mt++)
                    ldmA(a[mt], a_base + (mt * 16 * AST + aoff + kc) * 2);
#pragma unroll
                for (int nt = 0; nt < 4; nt++)
                    ldmB(bb[nt], b_base0 + ((boff + kc) * WBS + nt * 8) * 2);
#pragma unroll
                for (int mt = 0; mt < 2; mt++)
#pragma unroll
                    for (int nt = 0; nt < 4; nt++)
                        mma16816(c2[mt][nt], a[mt], bb[nt]);
            }
        }
        __syncwarp();
    }

    // --- epilogue: + bias, store out[oc][v]
    int gq = lane >> 2;
    int qq = lane & 3;
#pragma unroll
    for (int nt = 0; nt < 4; nt++) {
        int oc = nt * 8 + qq * 2;
        float b0 = __ldg(bfin + oc), b1 = __ldg(bfin + oc + 1);
        float* r0p = out + (size_t)oc * NVOX;
        float* r1p = out + (size_t)(oc + 1) * NVOX;
#pragma unroll
        for (int mt = 0; mt < 2; mt++) {
            int vv = v0 + wid * 32 + mt * 16 + gq;
            r0p[vv]     = c2[mt][nt][0] + b0;
            r1p[vv]     = c2[mt][nt][1] + b1;
            r0p[vv + 8] = c2[mt][nt][2] + b0;
            r1p[vv + 8] = c2[mt][nt][3] + b1;
        }
    }
}

// ---------------------------------------------------------------------------
static const float* pick(void* const* d_in, const int* in_sizes, int n_in, int want) {
    for (int i = 0; i < n_in; i++)
        if (in_sizes[i] == want) return (const float*)d_in[i];
    return nullptr;
}

extern "C" void kernel_launch(void* const* d_in, const int* in_sizes, int n_in,
                              void* d_out, int out_size) {
    const float* x      = pick(d_in, in_sizes, n_in, NVOX * CIN);
    const float* w_off  = pick(d_in, in_sizes, n_in, 81 * CIN * KK);
    const float* b_off  = pick(d_in, in_sizes, n_in, 81);
    const float* w_mask = pick(d_in, in_sizes, n_in, 27 * CIN * KK);
    const float* b_mask = pick(d_in, in_sizes, n_in, 27);
    const float* w      = pick(d_in, in_sizes, n_in, COUT * CIN * KK);
    const float* b      = pick(d_in, in_sizes, n_in, COUT);
    float* out = (float*)d_out;

    transpose_kernel<<<NVOX / 32, dim3(32, 8)>>>(x);
    reorg_kernel<<<(KK * 64 * BST + 255) / 256, 256>>>(w_off, b_off, w_mask, b_mask, w);
    conv_hmma_kernel<<<NVOX / 128, 256>>>();
    deform13_kernel<<<NVOX / 128, 128>>>(b, out);
}